// round 6
// baseline (speedup 1.0000x reference)
#include <cuda_runtime.h>
#include <cuda_fp16.h>
#include <cstdint>

#define BATCH 2
#define HEADS 16
#define SEQ   4096
#define DIM   64
#define WIN   512
#define HALF  256
#define NFULL 15
#define P0    3840
#define ROWS_PER_BH 7936
#define BH    (BATCH*HEADS)

__device__ float g_ws[(size_t)BH * ROWS_PER_BH * DIM];   // per-window outputs

#define KSTRIDE 72   // halves per smem row (64 data + 8 pad) -> conflict-free frags

__device__ __forceinline__ uint32_t pack_h2(float a, float b) {
    __half2 h = __floats2half2_rn(a, b);
    return *(uint32_t*)&h;
}
__device__ __forceinline__ float sigmoid_fast(float x) {
    float t;
    asm("tanh.approx.f32 %0, %1;" : "=f"(t) : "f"(x * 0.5f));
    return fmaf(t, 0.5f, 0.5f);
}
__device__ __forceinline__ void mma_f16(float c[4], const uint32_t a[4], uint32_t b0, uint32_t b1) {
    asm volatile(
        "mma.sync.aligned.m16n8k16.row.col.f32.f16.f16.f32 "
        "{%0,%1,%2,%3}, {%4,%5,%6,%7}, {%8,%9}, {%0,%1,%2,%3};"
        : "+f"(c[0]), "+f"(c[1]), "+f"(c[2]), "+f"(c[3])
        : "r"(a[0]), "r"(a[1]), "r"(a[2]), "r"(a[3]), "r"(b0), "r"(b1));
}

__global__ __launch_bounds__(256, 2)
void win_attn_h(const float* __restrict__ Q,
                const float* __restrict__ K,
                const float* __restrict__ V,
                const float* __restrict__ scale_p,
                int bh0)
{
    __shared__ __align__(16) __half smK[2][64 * KSTRIDE];  // [stage][key][dim]
    __shared__ __align__(16) __half smVT[2][64 * KSTRIDE]; // [stage][dim][key]

    const int tid  = threadIdx.x;
    const int lane = tid & 31;
    const int warp = tid >> 5;          // 0..7, owns q-rows [warp*16, warp*16+16)
    const int gid  = lane >> 2;         // 0..7
    const int tig  = lane & 3;          // 0..3

    const int bh = bh0 + blockIdx.y;
    const int t  = blockIdx.x;

    int nkeys, key_start, row0, qoff;
    if (t < 60) {
        int w = t >> 2, qt = t & 3;
        nkeys = WIN; key_start = w * HALF; row0 = w * WIN + qt * 128; qoff = qt * 128;
    } else {
        int qt = t - 60;
        nkeys = HALF; key_start = P0; row0 = NFULL * WIN + qt * 128; qoff = qt * 128;
    }
    const int nchunks = nkeys >> 6;
    const size_t base = (size_t)bh * SEQ * DIM;
    const float scale = *scale_p;

    // ---- Q fragments for m16n8k16 (A), fp16, scale folded in ----
    uint32_t qa[4][4];
    {
        const float* q0 = Q + base + (size_t)(key_start + qoff + warp * 16 + gid) * DIM;
        const float* q1 = q0 + 8 * DIM;
        #pragma unroll
        for (int ks = 0; ks < 4; ks++) {
            float2 v;
            v = *(const float2*)(q0 + ks * 16 + 2 * tig);
            qa[ks][0] = pack_h2(v.x * scale, v.y * scale);
            v = *(const float2*)(q1 + ks * 16 + 2 * tig);
            qa[ks][1] = pack_h2(v.x * scale, v.y * scale);
            v = *(const float2*)(q0 + ks * 16 + 2 * tig + 8);
            qa[ks][2] = pack_h2(v.x * scale, v.y * scale);
            v = *(const float2*)(q1 + ks * 16 + 2 * tig + 8);
            qa[ks][3] = pack_h2(v.x * scale, v.y * scale);
        }
    }

    float dacc[8][4];
    #pragma unroll
    for (int nt = 0; nt < 8; nt++)
        #pragma unroll
        for (int i = 0; i < 4; i++) dacc[nt][i] = 0.0f;
    float den0 = 0.0f, den1 = 0.0f;

    const int brow = gid * (KSTRIDE / 2) + tig;   // base uint-index offset for gid/tig

    // prefetch chunk 0 into registers
    float4 kreg[4], vreg[4];
    {
        const float4* kg = (const float4*)(K + base + (size_t)key_start * DIM);
        const float4* vg = (const float4*)(V + base + (size_t)key_start * DIM);
        #pragma unroll
        for (int i = 0; i < 4; i++) { kreg[i] = kg[tid + i * 256]; vreg[i] = vg[tid + i * 256]; }
    }

    for (int c = 0; c < nchunks; c++) {
        const int st = c & 1;
        // ---- store staged K (fp16, [key][dim]) and V^T (fp16, [dim][key]) into stage buffer ----
        __half* bK  = smK[st];
        __half* bVT = smVT[st];
        #pragma unroll
        for (int i = 0; i < 4; i++) {
            int idx = tid + i * 256;
            int r = idx >> 4, c4 = idx & 15;
            uint2 kk = { pack_h2(kreg[i].x, kreg[i].y), pack_h2(kreg[i].z, kreg[i].w) };
            *(uint2*)((char*)bK + r * (KSTRIDE * 2) + c4 * 8) = kk;
            bVT[(4 * c4 + 0) * KSTRIDE + r] = __float2half_rn(vreg[i].x);
            bVT[(4 * c4 + 1) * KSTRIDE + r] = __float2half_rn(vreg[i].y);
            bVT[(4 * c4 + 2) * KSTRIDE + r] = __float2half_rn(vreg[i].z);
            bVT[(4 * c4 + 3) * KSTRIDE + r] = __float2half_rn(vreg[i].w);
        }
        __syncthreads();   // stage st fully written (single sync per chunk)

        // prefetch next chunk (overlaps the MMAs below; lands in the other stage next iter)
        if (c + 1 < nchunks) {
            const int k1 = key_start + (c + 1) * 64;
            const float4* kg = (const float4*)(K + base + (size_t)k1 * DIM);
            const float4* vg = (const float4*)(V + base + (size_t)k1 * DIM);
            #pragma unroll
            for (int i = 0; i < 4; i++) { kreg[i] = kg[tid + i * 256]; vreg[i] = vg[tid + i * 256]; }
        }

        const uint32_t* sKu = (const uint32_t*)bK;
        const uint32_t* sVu = (const uint32_t*)bVT;

        // ---- MMA1 per n-tile + sigmoid -> register-resident P fragments ----
        uint32_t pa[4][4];
        #pragma unroll
        for (int nt = 0; nt < 8; nt++) {
            float sl[4] = {0.0f, 0.0f, 0.0f, 0.0f};
            const int rb = nt * 8 * (KSTRIDE / 2) + brow;
            #pragma unroll
            for (int ks = 0; ks < 4; ks++) {
                uint32_t b0 = sKu[rb + 8 * ks];
                uint32_t b1 = sKu[rb + 8 * ks + 4];
                mma_f16(sl, qa[ks], b0, b1);
            }
            float p0 = sigmoid_fast(sl[0]);
            float p1 = sigmoid_fast(sl[1]);
            float p2 = sigmoid_fast(sl[2]);
            float p3 = sigmoid_fast(sl[3]);
            uint32_t u01 = pack_h2(p0, p1);
            uint32_t u23 = pack_h2(p2, p3);
            float2 f01 = __half22float2(*(__half2*)&u01);
            float2 f23 = __half22float2(*(__half2*)&u23);
            den0 += f01.x + f01.y;
            den1 += f23.x + f23.y;
            int kc = nt >> 1, hi = (nt & 1) * 2;
            pa[kc][hi]     = u01;
            pa[kc][hi + 1] = u23;
        }

        // ---- MMA2: D += P . V  (A = pa, B from V^T tile) ----
        #pragma unroll
        for (int kc = 0; kc < 4; kc++) {
            #pragma unroll
            for (int nt = 0; nt < 8; nt++) {
                const int rb = nt * 8 * (KSTRIDE / 2) + brow;
                uint32_t b0 = sVu[rb + 8 * kc];
                uint32_t b1 = sVu[rb + 8 * kc + 4];
                mma_f16(dacc[nt], pa[kc], b0, b1);
            }
        }
    }

    // ---- denom reduce within quad ----
    den0 += __shfl_xor_sync(0xFFFFFFFF, den0, 1);
    den0 += __shfl_xor_sync(0xFFFFFFFF, den0, 2);
    den1 += __shfl_xor_sync(0xFFFFFFFF, den1, 1);
    den1 += __shfl_xor_sync(0xFFFFFFFF, den1, 2);
    const float inv0 = 1.0f / den0;
    const float inv1 = 1.0f / den1;

    // ---- epilogue: D/denom -> g_ws ----
    {
        float* o0 = g_ws + ((size_t)bh * ROWS_PER_BH + row0 + warp * 16 + gid) * DIM;
        float* o1 = o0 + 8 * DIM;
        #pragma unroll
        for (int nt = 0; nt < 8; nt++) {
            float2 r0 = { dacc[nt][0] * inv0, dacc[nt][1] * inv0 };
            float2 r1 = { dacc[nt][2] * inv1, dacc[nt][3] * inv1 };
            *(float2*)(o0 + nt * 8 + 2 * tig) = r0;
            *(float2*)(o1 + nt * 8 + 2 * tig) = r1;
        }
    }
}

// ---------------- Blend ----------------
__global__ __launch_bounds__(256)
void blend_kernel(float* __restrict__ out, int bh0)
{
    const int D4 = DIM / 4;
    size_t tid = (size_t)blockIdx.x * blockDim.x + threadIdx.x;
    const size_t total = (size_t)(BH / 2) * SEQ * D4;
    if (tid >= total) return;

    int d4 = (int)(tid % D4);
    size_t r = tid / D4;
    int s  = (int)(r % SEQ);
    int bh = bh0 + (int)(r / SEQ);

    int k = s >> 8;
    int i = s & 255;
    float a = (float)i * (1.0f / 255.0f);

    const float4* ws = (const float4*)(g_ws + (size_t)bh * ROWS_PER_BH * DIM);

    float4 res;
    if (k == 0) {
        res = ws[(size_t)i * D4 + d4];
    } else if (k < NFULL) {
        float4 v0 = ws[(size_t)((k - 1) * WIN + HALF + i) * D4 + d4];
        float4 v1 = ws[(size_t)(k * WIN + i) * D4 + d4];
        res.x = (1.0f - a) * v0.x + a * v1.x;
        res.y = (1.0f - a) * v0.y + a * v1.y;
        res.z = (1.0f - a) * v0.z + a * v1.z;
        res.w = (1.0f - a) * v0.w + a * v1.w;
    } else {
        float4 v0 = ws[(size_t)((NFULL - 1) * WIN + HALF + i) * D4 + d4];
        float4 v1 = ws[(size_t)(NFULL * WIN + i) * D4 + d4];
        res.x = (1.0f - a) * v0.x + a * v1.x;
        res.y = (1.0f - a) * v0.y + a * v1.y;
        res.z = (1.0f - a) * v0.z + a * v1.z;
        res.w = (1.0f - a) * v0.w + a * v1.w;
    }
    float4* ob = (float4*)out + (size_t)bh0 * SEQ * D4;
    ob[tid] = res;
}

extern "C" void kernel_launch(void* const* d_in, const int* in_sizes, int n_in,
                              void* d_out, int out_size)
{
    const float* Q     = (const float*)d_in[0];
    const float* K     = (const float*)d_in[1];
    const float* V     = (const float*)d_in[2];
    const float* scale = (const float*)d_in[3];
    float* out = (float*)d_out;

    // Split each kernel into two half-grid launches (bh halves).
    // Perf-neutral; makes ncu's launch #5 land on win_attn_h for profiling.
    dim3 grid(62, BH / 2);
    win_attn_h<<<grid, 256>>>(Q, K, V, scale, 0);
    win_attn_h<<<grid, 256>>>(Q, K, V, scale, BH / 2);

    const size_t total4 = (size_t)(BH / 2) * SEQ * (DIM / 4);
    int blocks = (int)((total4 + 255) / 256);
    blend_kernel<<<blocks, 256>>>(out, 0);
    blend_kernel<<<blocks, 256>>>(out, BH / 2);
}

// round 7
// speedup vs baseline: 1.0977x; 1.0977x over previous
#include <cuda_runtime.h>
#include <cuda_fp16.h>
#include <cstdint>

#define BATCH 2
#define HEADS 16
#define SEQ   4096
#define DIM   64
#define WIN   512
#define HALF  256
#define NFULL 15
#define P0    3840
#define ROWS_PER_BH 7936
#define BH    (BATCH*HEADS)

__device__ float g_ws[(size_t)BH * ROWS_PER_BH * DIM];   // per-window outputs

#define KSTRIDE 72   // halves per smem row (64 data + 8 pad) -> conflict-free frags

__device__ __forceinline__ uint32_t pack_h2(float a, float b) {
    __half2 h = __floats2half2_rn(a, b);
    return *(uint32_t*)&h;
}
__device__ __forceinline__ void mma_f16(float c[4], const uint32_t a[4], uint32_t b0, uint32_t b1) {
    asm volatile(
        "mma.sync.aligned.m16n8k16.row.col.f32.f16.f16.f32 "
        "{%0,%1,%2,%3}, {%4,%5,%6,%7}, {%8,%9}, {%0,%1,%2,%3};"
        : "+f"(c[0]), "+f"(c[1]), "+f"(c[2]), "+f"(c[3])
        : "r"(a[0]), "r"(a[1]), "r"(a[2]), "r"(a[3]), "r"(b0), "r"(b1));
}
// packed sigmoid: p = 0.5*tanh(0.5*x) + 0.5 on two fp16 lanes
__device__ __forceinline__ uint32_t sigmoid_h2(float x0, float x1) {
    __half2 h = __floats2half2_rn(x0 * 0.5f, x1 * 0.5f);
    uint32_t t;
    asm("tanh.approx.f16x2 %0, %1;" : "=r"(t) : "r"(*(uint32_t*)&h));
    const __half2 c05 = __floats2half2_rn(0.5f, 0.5f);
    __half2 p = __hfma2(*(__half2*)&t, c05, c05);
    return *(uint32_t*)&p;
}

__global__ __launch_bounds__(256, 2)
void win_attn_h(const float* __restrict__ Q,
                const float* __restrict__ K,
                const float* __restrict__ V,
                const float* __restrict__ scale_p)
{
    __shared__ __align__(16) __half smK[2][64 * KSTRIDE];  // [stage][key][dim]
    __shared__ __align__(16) __half smVT[2][64 * KSTRIDE]; // [stage][dim][key]

    const int tid  = threadIdx.x;
    const int lane = tid & 31;
    const int warp = tid >> 5;          // 0..7, owns q-rows [warp*16, warp*16+16)
    const int gid  = lane >> 2;         // 0..7
    const int tig  = lane & 3;          // 0..3

    const int bh = blockIdx.y;
    const int t  = blockIdx.x;

    int nkeys, key_start, row0, qoff;
    if (t < 60) {
        int w = t >> 2, qt = t & 3;
        nkeys = WIN; key_start = w * HALF; row0 = w * WIN + qt * 128; qoff = qt * 128;
    } else {
        int qt = t - 60;
        nkeys = HALF; key_start = P0; row0 = NFULL * WIN + qt * 128; qoff = qt * 128;
    }
    const int nchunks = nkeys >> 6;
    const size_t base = (size_t)bh * SEQ * DIM;
    const float scale = *scale_p;

    // ---- Q fragments for m16n8k16 (A), fp16, scale folded in ----
    uint32_t qa[4][4];
    {
        const float* q0 = Q + base + (size_t)(key_start + qoff + warp * 16 + gid) * DIM;
        const float* q1 = q0 + 8 * DIM;
        #pragma unroll
        for (int ks = 0; ks < 4; ks++) {
            float2 v;
            v = *(const float2*)(q0 + ks * 16 + 2 * tig);
            qa[ks][0] = pack_h2(v.x * scale, v.y * scale);
            v = *(const float2*)(q1 + ks * 16 + 2 * tig);
            qa[ks][1] = pack_h2(v.x * scale, v.y * scale);
            v = *(const float2*)(q0 + ks * 16 + 2 * tig + 8);
            qa[ks][2] = pack_h2(v.x * scale, v.y * scale);
            v = *(const float2*)(q1 + ks * 16 + 2 * tig + 8);
            qa[ks][3] = pack_h2(v.x * scale, v.y * scale);
        }
    }

    float dacc[8][4];
    #pragma unroll
    for (int nt = 0; nt < 8; nt++)
        #pragma unroll
        for (int i = 0; i < 4; i++) dacc[nt][i] = 0.0f;
    float den0 = 0.0f, den1 = 0.0f;

    const int brow = gid * (KSTRIDE / 2) + tig;   // base uint-index offset for gid/tig

    // prefetch chunk 0 into registers
    float4 kreg[4], vreg[4];
    {
        const float4* kg = (const float4*)(K + base + (size_t)key_start * DIM);
        const float4* vg = (const float4*)(V + base + (size_t)key_start * DIM);
        #pragma unroll
        for (int i = 0; i < 4; i++) { kreg[i] = kg[tid + i * 256]; vreg[i] = vg[tid + i * 256]; }
    }

    for (int c = 0; c < nchunks; c++) {
        const int st = c & 1;
        __half* bK  = smK[st];
        __half* bVT = smVT[st];
        // ---- store staged K (fp16, [key][dim]) and V^T (fp16, [dim][key]) ----
        #pragma unroll
        for (int i = 0; i < 4; i++) {
            int idx = tid + i * 256;
            int r = idx >> 4, c4 = idx & 15;
            uint2 kk = { pack_h2(kreg[i].x, kreg[i].y), pack_h2(kreg[i].z, kreg[i].w) };
            *(uint2*)((char*)bK + r * (KSTRIDE * 2) + c4 * 8) = kk;
            bVT[(4 * c4 + 0) * KSTRIDE + r] = __float2half_rn(vreg[i].x);
            bVT[(4 * c4 + 1) * KSTRIDE + r] = __float2half_rn(vreg[i].y);
            bVT[(4 * c4 + 2) * KSTRIDE + r] = __float2half_rn(vreg[i].z);
            bVT[(4 * c4 + 3) * KSTRIDE + r] = __float2half_rn(vreg[i].w);
        }

        // prefetch next chunk BEFORE the barrier (LDG latency overlaps the sync)
        if (c + 1 < nchunks) {
            const int k1 = key_start + (c + 1) * 64;
            const float4* kg = (const float4*)(K + base + (size_t)k1 * DIM);
            const float4* vg = (const float4*)(V + base + (size_t)k1 * DIM);
            #pragma unroll
            for (int i = 0; i < 4; i++) { kreg[i] = kg[tid + i * 256]; vreg[i] = vg[tid + i * 256]; }
        }
        __syncthreads();   // stage st fully written; single sync per chunk (double-buffered)

        const uint32_t* sKu = (const uint32_t*)bK;
        const uint32_t* sVu = (const uint32_t*)bVT;

        // ---- MMA1 per n-tile + packed sigmoid -> register-resident P fragments ----
        uint32_t pa[4][4];
        #pragma unroll
        for (int nt = 0; nt < 8; nt++) {
            float sl[4] = {0.0f, 0.0f, 0.0f, 0.0f};
            const int rb = nt * 8 * (KSTRIDE / 2) + brow;
            #pragma unroll
            for (int ks = 0; ks < 4; ks++) {
                uint32_t b0 = sKu[rb + 8 * ks];
                uint32_t b1 = sKu[rb + 8 * ks + 4];
                mma_f16(sl, qa[ks], b0, b1);
            }
            uint32_t u01 = sigmoid_h2(sl[0], sl[1]);
            uint32_t u23 = sigmoid_h2(sl[2], sl[3]);
            // denom from the fp16-rounded values (consistency with MMA2 numerator)
            float2 f01 = __half22float2(*(__half2*)&u01);
            float2 f23 = __half22float2(*(__half2*)&u23);
            den0 += f01.x + f01.y;
            den1 += f23.x + f23.y;
            int kc = nt >> 1, hi = (nt & 1) * 2;
            pa[kc][hi]     = u01;
            pa[kc][hi + 1] = u23;
        }

        // ---- MMA2: D += P . V  (A = pa, B from V^T tile) ----
        #pragma unroll
        for (int kc = 0; kc < 4; kc++) {
            #pragma unroll
            for (int nt = 0; nt < 8; nt++) {
                const int rb = nt * 8 * (KSTRIDE / 2) + brow;
                uint32_t b0 = sVu[rb + 8 * kc];
                uint32_t b1 = sVu[rb + 8 * kc + 4];
                mma_f16(dacc[nt], pa[kc], b0, b1);
            }
        }
    }

    // ---- denom reduce within quad ----
    den0 += __shfl_xor_sync(0xFFFFFFFF, den0, 1);
    den0 += __shfl_xor_sync(0xFFFFFFFF, den0, 2);
    den1 += __shfl_xor_sync(0xFFFFFFFF, den1, 1);
    den1 += __shfl_xor_sync(0xFFFFFFFF, den1, 2);
    const float inv0 = 1.0f / den0;
    const float inv1 = 1.0f / den1;

    // ---- epilogue: D/denom -> g_ws ----
    {
        float* o0 = g_ws + ((size_t)bh * ROWS_PER_BH + row0 + warp * 16 + gid) * DIM;
        float* o1 = o0 + 8 * DIM;
        #pragma unroll
        for (int nt = 0; nt < 8; nt++) {
            float2 r0 = { dacc[nt][0] * inv0, dacc[nt][1] * inv0 };
            float2 r1 = { dacc[nt][2] * inv1, dacc[nt][3] * inv1 };
            *(float2*)(o0 + nt * 8 + 2 * tig) = r0;
            *(float2*)(o1 + nt * 8 + 2 * tig) = r1;
        }
    }
}

// ---------------- Blend ----------------
__global__ __launch_bounds__(256)
void blend_kernel(float* __restrict__ out)
{
    const int D4 = DIM / 4;
    size_t tid = (size_t)blockIdx.x * blockDim.x + threadIdx.x;
    const size_t total = (size_t)BH * SEQ * D4;
    if (tid >= total) return;

    int d4 = (int)(tid % D4);
    size_t r = tid / D4;
    int s  = (int)(r % SEQ);
    int bh = (int)(r / SEQ);

    int k = s >> 8;
    int i = s & 255;
    float a = (float)i * (1.0f / 255.0f);

    const float4* ws = (const float4*)(g_ws + (size_t)bh * ROWS_PER_BH * DIM);

    float4 res;
    if (k == 0) {
        res = ws[(size_t)i * D4 + d4];
    } else if (k < NFULL) {
        float4 v0 = ws[(size_t)((k - 1) * WIN + HALF + i) * D4 + d4];
        float4 v1 = ws[(size_t)(k * WIN + i) * D4 + d4];
        res.x = (1.0f - a) * v0.x + a * v1.x;
        res.y = (1.0f - a) * v0.y + a * v1.y;
        res.z = (1.0f - a) * v0.z + a * v1.z;
        res.w = (1.0f - a) * v0.w + a * v1.w;
    } else {
        float4 v0 = ws[(size_t)((NFULL - 1) * WIN + HALF + i) * D4 + d4];
        float4 v1 = ws[(size_t)(NFULL * WIN + i) * D4 + d4];
        res.x = (1.0f - a) * v0.x + a * v1.x;
        res.y = (1.0f - a) * v0.y + a * v1.y;
        res.z = (1.0f - a) * v0.z + a * v1.z;
        res.w = (1.0f - a) * v0.w + a * v1.w;
    }
    ((float4*)out)[tid] = res;
}

extern "C" void kernel_launch(void* const* d_in, const int* in_sizes, int n_in,
                              void* d_out, int out_size)
{
    const float* Q     = (const float*)d_in[0];
    const float* K     = (const float*)d_in[1];
    const float* V     = (const float*)d_in[2];
    const float* scale = (const float*)d_in[3];
    float* out = (float*)d_out;

    dim3 grid(62, BH);
    win_attn_h<<<grid, 256>>>(Q, K, V, scale);

    const size_t total4 = (size_t)BH * SEQ * (DIM / 4);
    int blocks = (int)((total4 + 255) / 256);
    blend_kernel<<<blocks, 256>>>(out);
}

// round 8
// speedup vs baseline: 1.2904x; 1.1756x over previous
#include <cuda_runtime.h>
#include <cuda_fp16.h>
#include <cstdint>

#define BATCH 2
#define HEADS 16
#define SEQ   4096
#define DIM   64
#define WIN   512
#define HALF  256
#define NFULL 15
#define P0    3840
#define ROWS_PER_BH 7936
#define BH    (BATCH*HEADS)

__device__ float g_ws[(size_t)BH * ROWS_PER_BH * DIM];              // per-window outputs
__device__ __align__(16) __half g_kh[(size_t)BH * SEQ * DIM];       // K fp16 [bh][s][d]
__device__ __align__(16) __half g_vt[(size_t)BH * DIM * SEQ];       // V fp16 transposed [bh][d][s]

#define KSTRIDE 72            // halves per smem row (64 data + 8 pad)
#define ROWB    144           // bytes per smem row
#define TILE_B  (64*ROWB)     // 9216 B per K or VT tile
#define STAGE_B (2*TILE_B)    // 18432 B per stage (K + VT)
#define NSTAGE  3
#define SMEM_BYTES (NSTAGE*STAGE_B)   // 55296

__device__ __forceinline__ uint32_t pack_h2(float a, float b) {
    __half2 h = __floats2half2_rn(a, b);
    return *(uint32_t*)&h;
}
__device__ __forceinline__ void mma_f16(float c[4], const uint32_t a[4], uint32_t b0, uint32_t b1) {
    asm volatile(
        "mma.sync.aligned.m16n8k16.row.col.f32.f16.f16.f32 "
        "{%0,%1,%2,%3}, {%4,%5,%6,%7}, {%8,%9}, {%0,%1,%2,%3};"
        : "+f"(c[0]), "+f"(c[1]), "+f"(c[2]), "+f"(c[3])
        : "r"(a[0]), "r"(a[1]), "r"(a[2]), "r"(a[3]), "r"(b0), "r"(b1));
}
// packed sigmoid: p = 0.5*tanh(0.5*x) + 0.5 on two fp16 lanes
__device__ __forceinline__ uint32_t sigmoid_h2(float x0, float x1) {
    __half2 h = __floats2half2_rn(x0 * 0.5f, x1 * 0.5f);
    uint32_t t;
    asm("tanh.approx.f16x2 %0, %1;" : "=r"(t) : "r"(*(uint32_t*)&h));
    const __half2 c05 = __floats2half2_rn(0.5f, 0.5f);
    __half2 p = __hfma2(*(__half2*)&t, c05, c05);
    return *(uint32_t*)&p;
}
__device__ __forceinline__ uint32_t smem_u32(const void* p) {
    uint32_t a;
    asm("{ .reg .u64 t; cvta.to.shared.u64 t, %1; cvt.u32.u64 %0, t; }" : "=r"(a) : "l"(p));
    return a;
}
__device__ __forceinline__ void cp16(uint32_t dst, const void* src) {
    asm volatile("cp.async.cg.shared.global [%0], [%1], 16;" :: "r"(dst), "l"(src));
}

// ---------------- prep: K -> fp16 (same layout), V -> fp16 transposed ----------------
__global__ __launch_bounds__(256)
void prep_kv(const float* __restrict__ K, const float* __restrict__ V)
{
    __shared__ float tile[32][65];
    const int bh = blockIdx.y;
    const int s0 = blockIdx.x * 32;
    const int tid = threadIdx.x;

    const float* ks = K + ((size_t)bh * SEQ + s0) * DIM;
    const float* vs = V + ((size_t)bh * SEQ + s0) * DIM;
    __half* kd = g_kh + ((size_t)bh * SEQ + s0) * DIM;

    #pragma unroll
    for (int i = 0; i < 8; i++) {
        int w = tid + i * 256;          // 2048 = 32 rows x 64 dims
        int s = w >> 6, d = w & 63;
        kd[w] = __float2half_rn(ks[w]);
        tile[s][d] = vs[w];
    }
    __syncthreads();
    #pragma unroll
    for (int i = 0; i < 8; i++) {
        int w = tid + i * 256;
        int d = w >> 5, s = w & 31;
        g_vt[((size_t)bh * DIM + d) * SEQ + s0 + s] = __float2half_rn(tile[s][d]);
    }
}

__global__ void noop_kernel() {}

// ---------------- main attention kernel ----------------
__global__ __launch_bounds__(256, 2)
void win_attn_a(const float* __restrict__ Q,
                const float* __restrict__ scale_p)
{
    extern __shared__ __align__(16) char dsm[];
    const uint32_t sbase = smem_u32(dsm);

    const int tid  = threadIdx.x;
    const int lane = tid & 31;
    const int warp = tid >> 5;
    const int gid  = lane >> 2;
    const int tig  = lane & 3;

    const int bh = blockIdx.y;
    const int t  = blockIdx.x;

    int nkeys, key_start, row0, qoff;
    if (t < 60) {
        int w = t >> 2, qt = t & 3;
        nkeys = WIN; key_start = w * HALF; row0 = w * WIN + qt * 128; qoff = qt * 128;
    } else {
        int qt = t - 60;
        nkeys = HALF; key_start = P0; row0 = NFULL * WIN + qt * 128; qoff = qt * 128;
    }
    const int nchunks = nkeys >> 6;
    const float scale = *scale_p;

    const char* kh_bh = (const char*)(g_kh + (size_t)bh * SEQ * DIM);  // row = key, 128 B
    const char* vt_bh = (const char*)(g_vt + (size_t)bh * DIM * SEQ);  // row = dim, 8192 B stride

    // cp.async issue for one chunk into one stage (macro-ish lambda)
    auto issue = [&](int cc, int st) {
        const uint32_t sb = sbase + st * STAGE_B;
        const char* kg = kh_bh + (size_t)(key_start + cc * 64) * 128;
        const char* vg = vt_bh + (size_t)(key_start + cc * 64) * 2;
        #pragma unroll
        for (int i = 0; i < 2; i++) {
            int idx = tid + i * 256;
            int r = idx >> 3, c16 = (idx & 7) * 16;
            cp16(sb + r * ROWB + c16,          kg + r * 128 + c16);
            cp16(sb + TILE_B + r * ROWB + c16, vg + (size_t)r * 8192 + c16);
        }
    };

    // ---- Q fragments (m16n8k16 A), fp16, scale folded in ----
    uint32_t qa[4][4];
    {
        const size_t base = (size_t)bh * SEQ * DIM;
        const float* q0 = Q + base + (size_t)(key_start + qoff + warp * 16 + gid) * DIM;
        const float* q1 = q0 + 8 * DIM;
        #pragma unroll
        for (int ks = 0; ks < 4; ks++) {
            float2 v;
            v = *(const float2*)(q0 + ks * 16 + 2 * tig);
            qa[ks][0] = pack_h2(v.x * scale, v.y * scale);
            v = *(const float2*)(q1 + ks * 16 + 2 * tig);
            qa[ks][1] = pack_h2(v.x * scale, v.y * scale);
            v = *(const float2*)(q0 + ks * 16 + 2 * tig + 8);
            qa[ks][2] = pack_h2(v.x * scale, v.y * scale);
            v = *(const float2*)(q1 + ks * 16 + 2 * tig + 8);
            qa[ks][3] = pack_h2(v.x * scale, v.y * scale);
        }
    }

    // prologue: prefetch chunks 0 and 1
    issue(0, 0);
    asm volatile("cp.async.commit_group;" ::: "memory");
    issue(1, 1);
    asm volatile("cp.async.commit_group;" ::: "memory");

    float dacc[8][4];
    #pragma unroll
    for (int nt = 0; nt < 8; nt++)
        #pragma unroll
        for (int i = 0; i < 4; i++) dacc[nt][i] = 0.0f;
    float den0 = 0.0f, den1 = 0.0f;

    const int brow = gid * (KSTRIDE / 2) + tig;

    for (int c = 0; c < nchunks; c++) {
        asm volatile("cp.async.wait_group 1;" ::: "memory");
        __syncthreads();                       // chunk c resident; all warps past compute(c-1)

        const int st = c % NSTAGE;
        const uint32_t* sKu = (const uint32_t*)(dsm + st * STAGE_B);
        const uint32_t* sVu = (const uint32_t*)(dsm + st * STAGE_B + TILE_B);

        // prefetch chunk c+2 into the stage last read at chunk c-1
        if (c + 2 < nchunks) issue(c + 2, (c + 2) % NSTAGE);
        asm volatile("cp.async.commit_group;" ::: "memory");

        // ---- MMA1 per n-tile + packed sigmoid -> register-resident P ----
        uint32_t pa[4][4];
        #pragma unroll
        for (int nt = 0; nt < 8; nt++) {
            float sl[4] = {0.0f, 0.0f, 0.0f, 0.0f};
            const int rb = nt * 8 * (KSTRIDE / 2) + brow;
            #pragma unroll
            for (int ks = 0; ks < 4; ks++) {
                uint32_t b0 = sKu[rb + 8 * ks];
                uint32_t b1 = sKu[rb + 8 * ks + 4];
                mma_f16(sl, qa[ks], b0, b1);
            }
            uint32_t u01 = sigmoid_h2(sl[0], sl[1]);
            uint32_t u23 = sigmoid_h2(sl[2], sl[3]);
            float2 f01 = __half22float2(*(__half2*)&u01);
            float2 f23 = __half22float2(*(__half2*)&u23);
            den0 += f01.x + f01.y;
            den1 += f23.x + f23.y;
            int kc = nt >> 1, hi = (nt & 1) * 2;
            pa[kc][hi]     = u01;
            pa[kc][hi + 1] = u23;
        }

        // ---- MMA2: D += P . V ----
        #pragma unroll
        for (int kc = 0; kc < 4; kc++) {
            #pragma unroll
            for (int nt = 0; nt < 8; nt++) {
                const int rb = nt * 8 * (KSTRIDE / 2) + brow;
                uint32_t b0 = sVu[rb + 8 * kc];
                uint32_t b1 = sVu[rb + 8 * kc + 4];
                mma_f16(dacc[nt], pa[kc], b0, b1);
            }
        }
    }

    // ---- denom reduce within quad ----
    den0 += __shfl_xor_sync(0xFFFFFFFF, den0, 1);
    den0 += __shfl_xor_sync(0xFFFFFFFF, den0, 2);
    den1 += __shfl_xor_sync(0xFFFFFFFF, den1, 1);
    den1 += __shfl_xor_sync(0xFFFFFFFF, den1, 2);
    const float inv0 = 1.0f / den0;
    const float inv1 = 1.0f / den1;

    // ---- epilogue: D/denom -> g_ws ----
    {
        float* o0 = g_ws + ((size_t)bh * ROWS_PER_BH + row0 + warp * 16 + gid) * DIM;
        float* o1 = o0 + 8 * DIM;
        #pragma unroll
        for (int nt = 0; nt < 8; nt++) {
            float2 r0 = { dacc[nt][0] * inv0, dacc[nt][1] * inv0 };
            float2 r1 = { dacc[nt][2] * inv1, dacc[nt][3] * inv1 };
            *(float2*)(o0 + nt * 8 + 2 * tig) = r0;
            *(float2*)(o1 + nt * 8 + 2 * tig) = r1;
        }
    }
}

// ---------------- Blend ----------------
__global__ __launch_bounds__(256)
void blend_kernel(float* __restrict__ out)
{
    const int D4 = DIM / 4;
    size_t tid = (size_t)blockIdx.x * blockDim.x + threadIdx.x;
    const size_t total = (size_t)BH * SEQ * D4;
    if (tid >= total) return;

    int d4 = (int)(tid % D4);
    size_t r = tid / D4;
    int s  = (int)(r % SEQ);
    int bh = (int)(r / SEQ);

    int k = s >> 8;
    int i = s & 255;
    float a = (float)i * (1.0f / 255.0f);

    const float4* ws = (const float4*)(g_ws + (size_t)bh * ROWS_PER_BH * DIM);

    float4 res;
    if (k == 0) {
        res = ws[(size_t)i * D4 + d4];
    } else if (k < NFULL) {
        float4 v0 = ws[(size_t)((k - 1) * WIN + HALF + i) * D4 + d4];
        float4 v1 = ws[(size_t)(k * WIN + i) * D4 + d4];
        res.x = (1.0f - a) * v0.x + a * v1.x;
        res.y = (1.0f - a) * v0.y + a * v1.y;
        res.z = (1.0f - a) * v0.z + a * v1.z;
        res.w = (1.0f - a) * v0.w + a * v1.w;
    } else {
        float4 v0 = ws[(size_t)((NFULL - 1) * WIN + HALF + i) * D4 + d4];
        float4 v1 = ws[(size_t)(NFULL * WIN + i) * D4 + d4];
        res.x = (1.0f - a) * v0.x + a * v1.x;
        res.y = (1.0f - a) * v0.y + a * v1.y;
        res.z = (1.0f - a) * v0.z + a * v1.z;
        res.w = (1.0f - a) * v0.w + a * v1.w;
    }
    ((float4*)out)[tid] = res;
}

extern "C" void kernel_launch(void* const* d_in, const int* in_sizes, int n_in,
                              void* d_out, int out_size)
{
    const float* Q     = (const float*)d_in[0];
    const float* K     = (const float*)d_in[1];
    const float* V     = (const float*)d_in[2];
    const float* scale = (const float*)d_in[3];
    float* out = (float*)d_out;

    static bool attr_set = false;
    if (!attr_set) {
        cudaFuncSetAttribute(win_attn_a, cudaFuncAttributeMaxDynamicSharedMemorySize, SMEM_BYTES);
        attr_set = true;
    }

    dim3 pgrid(SEQ / 32, BH);
    prep_kv<<<pgrid, 256>>>(K, V);

    dim3 grid(62, BH);
    win_attn_a<<<grid, 256, SMEM_BYTES>>>(Q, scale);

    const size_t total4 = (size_t)BH * SEQ * (DIM / 4);
    int blocks = (int)((total4 + 255) / 256);
    blend_kernel<<<blocks, 256>>>(out);

    // 4th launch: makes ncu -s 5 -c 1 land on win_attn_a (launch index 5 = 4*1+1)
    noop_kernel<<<1, 1>>>();
}

// round 9
// speedup vs baseline: 1.6199x; 1.2553x over previous
#include <cuda_runtime.h>
#include <cuda_fp16.h>
#include <cstdint>

#define BATCH 2
#define HEADS 16
#define SEQ   4096
#define DIM   64
#define WIN   512
#define HALF  256
#define NSEG  16              // output segments of 256 queries
#define BH    (BATCH*HEADS)

__device__ __align__(16) __half g_kh[(size_t)BH * SEQ * DIM];   // K fp16 [bh][s][d]
__device__ __align__(16) __half g_vt[(size_t)BH * DIM * SEQ];   // V fp16 transposed [bh][d][s]

#define KSTRIDE 72            // halves per smem row (64 data + 8 pad)
#define ROWB    144           // bytes per smem row
#define TILE_B  (64*ROWB)     // 9216 B per K or VT tile
#define STAGE_B (2*TILE_B)    // 18432 B per stage (K + VT)
#define NSTAGE  3
#define SMEM_BYTES (NSTAGE*STAGE_B)   // 55296

__device__ __forceinline__ uint32_t pack_h2(float a, float b) {
    __half2 h = __floats2half2_rn(a, b);
    return *(uint32_t*)&h;
}
__device__ __forceinline__ void mma_f16(float c[4], const uint32_t a[4], uint32_t b0, uint32_t b1) {
    asm volatile(
        "mma.sync.aligned.m16n8k16.row.col.f32.f16.f16.f32 "
        "{%0,%1,%2,%3}, {%4,%5,%6,%7}, {%8,%9}, {%0,%1,%2,%3};"
        : "+f"(c[0]), "+f"(c[1]), "+f"(c[2]), "+f"(c[3])
        : "r"(a[0]), "r"(a[1]), "r"(a[2]), "r"(a[3]), "r"(b0), "r"(b1));
}
// packed sigmoid: p = 0.5*tanh(0.5*x) + 0.5 on two fp16 lanes
__device__ __forceinline__ uint32_t sigmoid_h2(float x0, float x1) {
    __half2 h = __floats2half2_rn(x0 * 0.5f, x1 * 0.5f);
    uint32_t t;
    asm("tanh.approx.f16x2 %0, %1;" : "=r"(t) : "r"(*(uint32_t*)&h));
    const __half2 c05 = __floats2half2_rn(0.5f, 0.5f);
    __half2 p = __hfma2(*(__half2*)&t, c05, c05);
    return *(uint32_t*)&p;
}
__device__ __forceinline__ uint32_t smem_u32(const void* p) {
    uint32_t a;
    asm("{ .reg .u64 t; cvta.to.shared.u64 t, %1; cvt.u32.u64 %0, t; }" : "=r"(a) : "l"(p));
    return a;
}
__device__ __forceinline__ void cp16(uint32_t dst, const void* src) {
    asm volatile("cp.async.cg.shared.global [%0], [%1], 16;" :: "r"(dst), "l"(src));
}

// ---------------- prep: K -> fp16 (same layout), V -> fp16 transposed ----------------
__global__ __launch_bounds__(256)
void prep_kv(const float* __restrict__ K, const float* __restrict__ V)
{
    __shared__ float tile[32][65];
    const int bh = blockIdx.y;
    const int s0 = blockIdx.x * 32;
    const int tid = threadIdx.x;

    const float* ks = K + ((size_t)bh * SEQ + s0) * DIM;
    const float* vs = V + ((size_t)bh * SEQ + s0) * DIM;
    __half* kd = g_kh + ((size_t)bh * SEQ + s0) * DIM;

    #pragma unroll
    for (int i = 0; i < 8; i++) {
        int w = tid + i * 256;
        int s = w >> 6, d = w & 63;
        kd[w] = __float2half_rn(ks[w]);
        tile[s][d] = vs[w];
    }
    __syncthreads();
    #pragma unroll
    for (int i = 0; i < 8; i++) {
        int w = tid + i * 256;
        int d = w >> 5, s = w & 31;
        g_vt[((size_t)bh * DIM + d) * SEQ + s0 + s] = __float2half_rn(tile[s][d]);
    }
}

// ---------------- fused attention + blend ----------------
// One CTA = 64 output queries of segment k. Key union range: 768 keys (mid),
// chunks 0..7 -> prev-window accum, chunks 4..11 -> next-window accum;
// overlap chunks 4..7 feed both (P computed once). Epilogue does the alpha-blend.
__global__ __launch_bounds__(128, 3)
void win_attn_f(const float* __restrict__ Q,
                const float* __restrict__ scale_p,
                float* __restrict__ out)
{
    extern __shared__ __align__(16) char dsm[];
    const uint32_t sbase = smem_u32(dsm);

    const int tid  = threadIdx.x;
    const int lane = tid & 31;
    const int warp = tid >> 5;          // 0..3, owns q-rows [warp*16, warp*16+16)
    const int gid  = lane >> 2;
    const int tig  = lane & 3;

    const int bh = blockIdx.y;
    const int k  = blockIdx.x >> 2;     // segment 0..15
    const int qt = blockIdx.x & 3;      // 64-query tile within segment

    const int key_base = (k == 0) ? 0 : (k - 1) * HALF;
    const int nchunks  = (k == 0 || k == NSEG - 1) ? 8 : 12;
    const int c_next   = (k == 0) ? 0 : 4;       // chunks >= c_next feed "next"
    const int q0s      = k * HALF + qt * 64;     // first query row of this CTA
    const float scale  = *scale_p;

    const char* kh_bh = (const char*)(g_kh + (size_t)bh * SEQ * DIM);
    const char* vt_bh = (const char*)(g_vt + (size_t)bh * DIM * SEQ);

    auto issue = [&](int cc, int st) {
        const uint32_t sb = sbase + st * STAGE_B;
        const char* kg = kh_bh + (size_t)(key_base + cc * 64) * 128;
        const char* vg = vt_bh + (size_t)(key_base + cc * 64) * 2;
        #pragma unroll
        for (int i = 0; i < 4; i++) {
            int idx = tid + i * 128;
            int r = idx >> 3, c16 = (idx & 7) * 16;
            cp16(sb + r * ROWB + c16,          kg + r * 128 + c16);
            cp16(sb + TILE_B + r * ROWB + c16, vg + (size_t)r * 8192 + c16);
        }
    };

    // ---- Q fragments (m16n8k16 A), fp16, scale folded in ----
    uint32_t qa[4][4];
    {
        const size_t base = (size_t)bh * SEQ * DIM;
        const float* q0 = Q + base + (size_t)(q0s + warp * 16 + gid) * DIM;
        const float* q1 = q0 + 8 * DIM;
        #pragma unroll
        for (int ks = 0; ks < 4; ks++) {
            float2 v;
            v = *(const float2*)(q0 + ks * 16 + 2 * tig);
            qa[ks][0] = pack_h2(v.x * scale, v.y * scale);
            v = *(const float2*)(q1 + ks * 16 + 2 * tig);
            qa[ks][1] = pack_h2(v.x * scale, v.y * scale);
            v = *(const float2*)(q0 + ks * 16 + 2 * tig + 8);
            qa[ks][2] = pack_h2(v.x * scale, v.y * scale);
            v = *(const float2*)(q1 + ks * 16 + 2 * tig + 8);
            qa[ks][3] = pack_h2(v.x * scale, v.y * scale);
        }
    }

    // prologue: prefetch chunks 0 and 1
    issue(0, 0);
    asm volatile("cp.async.commit_group;" ::: "memory");
    issue(1, 1);
    asm volatile("cp.async.commit_group;" ::: "memory");

    float dp[8][4], dn[8][4];
    #pragma unroll
    for (int nt = 0; nt < 8; nt++)
        #pragma unroll
        for (int i = 0; i < 4; i++) { dp[nt][i] = 0.0f; dn[nt][i] = 0.0f; }
    float denp0 = 0.0f, denp1 = 0.0f, denn0 = 0.0f, denn1 = 0.0f;

    const int brow = gid * (KSTRIDE / 2) + tig;

    for (int c = 0; c < nchunks; c++) {
        asm volatile("cp.async.wait_group 1;" ::: "memory");
        __syncthreads();

        const int st = c % NSTAGE;
        const uint32_t* sKu = (const uint32_t*)(dsm + st * STAGE_B);
        const uint32_t* sVu = (const uint32_t*)(dsm + st * STAGE_B + TILE_B);

        if (c + 2 < nchunks) issue(c + 2, (c + 2) % NSTAGE);
        asm volatile("cp.async.commit_group;" ::: "memory");

        const bool prev_on = (k > 0) && (c < 8);
        const bool next_on = (c >= c_next);

        // ---- MMA1 per n-tile + packed sigmoid -> register-resident P ----
        uint32_t pa[4][4];
        float dsum0 = 0.0f, dsum1 = 0.0f;
        #pragma unroll
        for (int nt = 0; nt < 8; nt++) {
            float sl[4] = {0.0f, 0.0f, 0.0f, 0.0f};
            const int rb = nt * 8 * (KSTRIDE / 2) + brow;
            #pragma unroll
            for (int ks = 0; ks < 4; ks++) {
                uint32_t b0 = sKu[rb + 8 * ks];
                uint32_t b1 = sKu[rb + 8 * ks + 4];
                mma_f16(sl, qa[ks], b0, b1);
            }
            uint32_t u01 = sigmoid_h2(sl[0], sl[1]);
            uint32_t u23 = sigmoid_h2(sl[2], sl[3]);
            float2 f01 = __half22float2(*(__half2*)&u01);
            float2 f23 = __half22float2(*(__half2*)&u23);
            dsum0 += f01.x + f01.y;
            dsum1 += f23.x + f23.y;
            int kc = nt >> 1, hi = (nt & 1) * 2;
            pa[kc][hi]     = u01;
            pa[kc][hi + 1] = u23;
        }
        if (prev_on) { denp0 += dsum0; denp1 += dsum1; }
        if (next_on) { denn0 += dsum0; denn1 += dsum1; }

        // ---- MMA2 into prev and/or next accumulators ----
        if (prev_on) {
            #pragma unroll
            for (int kc = 0; kc < 4; kc++)
                #pragma unroll
                for (int nt = 0; nt < 8; nt++) {
                    const int rb = nt * 8 * (KSTRIDE / 2) + brow;
                    mma_f16(dp[nt], pa[kc], sVu[rb + 8 * kc], sVu[rb + 8 * kc + 4]);
                }
        }
        if (next_on) {
            #pragma unroll
            for (int kc = 0; kc < 4; kc++)
                #pragma unroll
                for (int nt = 0; nt < 8; nt++) {
                    const int rb = nt * 8 * (KSTRIDE / 2) + brow;
                    mma_f16(dn[nt], pa[kc], sVu[rb + 8 * kc], sVu[rb + 8 * kc + 4]);
                }
        }
    }

    // ---- denominator reduce within quad ----
    denp0 += __shfl_xor_sync(0xFFFFFFFF, denp0, 1);
    denp0 += __shfl_xor_sync(0xFFFFFFFF, denp0, 2);
    denp1 += __shfl_xor_sync(0xFFFFFFFF, denp1, 1);
    denp1 += __shfl_xor_sync(0xFFFFFFFF, denp1, 2);
    denn0 += __shfl_xor_sync(0xFFFFFFFF, denn0, 1);
    denn0 += __shfl_xor_sync(0xFFFFFFFF, denn0, 2);
    denn1 += __shfl_xor_sync(0xFFFFFFFF, denn1, 1);
    denn1 += __shfl_xor_sync(0xFFFFFFFF, denn1, 2);

    const float invp0 = (k == 0) ? 0.0f : 1.0f / denp0;
    const float invp1 = (k == 0) ? 0.0f : 1.0f / denp1;
    const float invn0 = 1.0f / denn0;
    const float invn1 = 1.0f / denn1;

    // ---- alpha-blend epilogue: out = (1-a)*prev + a*next ----
    const int i0 = qt * 64 + warp * 16 + gid;   // position within segment (0..255)
    const float a0 = (k == 0) ? 1.0f : (float)i0 * (1.0f / 255.0f);
    const float a1 = (k == 0) ? 1.0f : (float)(i0 + 8) * (1.0f / 255.0f);

    float* o0 = out + ((size_t)bh * SEQ + q0s + warp * 16 + gid) * DIM;
    float* o1 = o0 + 8 * DIM;
    #pragma unroll
    for (int nt = 0; nt < 8; nt++) {
        float2 r0, r1;
        r0.x = (1.0f - a0) * dp[nt][0] * invp0 + a0 * dn[nt][0] * invn0;
        r0.y = (1.0f - a0) * dp[nt][1] * invp0 + a0 * dn[nt][1] * invn0;
        r1.x = (1.0f - a1) * dp[nt][2] * invp1 + a1 * dn[nt][2] * invn1;
        r1.y = (1.0f - a1) * dp[nt][3] * invp1 + a1 * dn[nt][3] * invn1;
        *(float2*)(o0 + nt * 8 + 2 * tig) = r0;
        *(float2*)(o1 + nt * 8 + 2 * tig) = r1;
    }
}

extern "C" void kernel_launch(void* const* d_in, const int* in_sizes, int n_in,
                              void* d_out, int out_size)
{
    const float* Q     = (const float*)d_in[0];
    const float* K     = (const float*)d_in[1];
    const float* V     = (const float*)d_in[2];
    const float* scale = (const float*)d_in[3];
    float* out = (float*)d_out;

    static bool attr_set = false;
    if (!attr_set) {
        cudaFuncSetAttribute(win_attn_f, cudaFuncAttributeMaxDynamicSharedMemorySize, SMEM_BYTES);
        attr_set = true;
    }

    dim3 pgrid(SEQ / 32, BH);
    prep_kv<<<pgrid, 256>>>(K, V);

    dim3 grid(NSEG * 4, BH);
    win_attn_f<<<grid, 128, SMEM_BYTES>>>(Q, scale, out);
}